// round 3
// baseline (speedup 1.0000x reference)
#include <cuda_runtime.h>
#include <math.h>

#define N_NODES 50000
#define N_EDGES 800000
#define ETOT    (N_EDGES + N_NODES)
#define G_GRAPHS 8

typedef unsigned long long u64;

__device__ __forceinline__ u64 pack2s(float a) {
    u64 r; asm("mov.b64 %0,{%1,%1};" : "=l"(r) : "f"(a)); return r;
}
__device__ __forceinline__ float2 unpk(u64 v) {
    float2 f; asm("mov.b64 {%0,%1},%2;" : "=f"(f.x), "=f"(f.y) : "l"(v)); return f;
}
__device__ __forceinline__ u64 ffma2(u64 a, u64 b, u64 c) {
    u64 d; asm("fma.rn.f32x2 %0,%1,%2,%3;" : "=l"(d) : "l"(a), "l"(b), "l"(c)); return d;
}

// ---------------- scratch ----------------
__device__ float d_xl1[N_NODES * 128];
__device__ float d_xr1[N_NODES * 128];
__device__ float d_h1 [N_NODES * 128];
__device__ float d_xl2[N_NODES * 192];
__device__ float d_xr2[N_NODES * 192];
__device__ float d_h2 [N_NODES * 192];
__device__ int   d_rowptr[N_NODES + 1];
__device__ int   d_counts[N_NODES];
__device__ int   d_cursor[N_NODES];
__device__ int2  d_csr[N_EDGES];                 // (src, eid) grouped by dst
__device__ float d_ealoop[N_NODES * 32];         // mean incoming edge attr
__device__ float d_alpha[(size_t)ETOT * 3];      // per-edge attention logits
__device__ float d_pool[G_GRAPHS * 192];

__device__ __forceinline__ float lr01(float x) { return x > 0.f ? x : 0.01f * x; }

// ---------------- CSR build ----------------
__global__ void zero_kernel() {
    int i = blockIdx.x * blockDim.x + threadIdx.x;
    if (i < N_NODES) { d_counts[i] = 0; d_cursor[i] = 0; }
    if (i < G_GRAPHS * 192) d_pool[i] = 0.f;
}

__global__ void hist_kernel(const int* __restrict__ dst) {
    int e = blockIdx.x * blockDim.x + threadIdx.x;
    if (e < N_EDGES) atomicAdd(&d_counts[dst[e]], 1);
}

__global__ void scan_kernel() {
    __shared__ int sh[1024];
    int t = threadIdx.x;
    const int CH = (N_NODES + 1023) / 1024;
    int lo = t * CH;
    int hi = min(lo + CH, N_NODES);
    int s = 0;
    for (int i = lo; i < hi; i++) s += d_counts[i];
    sh[t] = s;
    __syncthreads();
    for (int off = 1; off < 1024; off <<= 1) {
        int v = (t >= off) ? sh[t - off] : 0;
        __syncthreads();
        sh[t] += v;
        __syncthreads();
    }
    int run = (t > 0) ? sh[t - 1] : 0;
    for (int i = lo; i < hi; i++) { d_rowptr[i] = run; run += d_counts[i]; }
    if (t == 0) d_rowptr[N_NODES] = N_EDGES;
}

__global__ void scatter_kernel(const int* __restrict__ src, const int* __restrict__ dst) {
    int e = blockIdx.x * blockDim.x + threadIdx.x;
    if (e < N_EDGES) {
        int d = dst[e];
        int p = atomicAdd(&d_cursor[d], 1);
        d_csr[d_rowptr[d] + p] = make_int2(src[e], e);
    }
}

// ---------------- ea_loop = mean of incoming edge attrs per node ----------------
__global__ void ealoop_kernel(const float* __restrict__ ea) {
    int warp = threadIdx.x >> 5, lane = threadIdx.x & 31;
    int node = blockIdx.x * 8 + warp;
    if (node >= N_NODES) return;
    int r0 = d_rowptr[node], deg = d_rowptr[node + 1] - r0;
    float s = 0.f;
    for (int j = 0; j < deg; j++) {
        int eid = d_csr[r0 + j].y;
        s += ea[(size_t)eid * 32 + lane];
    }
    d_ealoop[(size_t)node * 32 + lane] = s * (1.f / (float)max(deg, 1));
}

// ---------------- GEMM: Y[M,Ncols] = X[M,128] @ W[128,Ncols] + bias ----------------
// 128m x 64n block, 256 threads, 8m x 4n per thread; A staged transposed.
__global__ __launch_bounds__(256) void gemm_k128(
    const float* __restrict__ Xin, int useH1,
    const float* __restrict__ W, const float* __restrict__ bias,
    int outSel, int M, int Ncols)
{
    const float* X = useH1 ? d_h1 : Xin;
    float* Y = (outSel == 0) ? d_xl1 : (outSel == 1) ? d_xr1 : (outSel == 2) ? d_xl2 : d_xr2;

    __shared__ float XsT[32 * 132];  // [k][m], stride 132 (16B-aligned rows)
    __shared__ float Ws [32 * 68];   // [k][n], stride 68

    int tid = threadIdx.x;
    int tx = tid & 15, ty = tid >> 4;
    int m0 = blockIdx.x * 128, n0 = blockIdx.y * 64;

    u64 acc[8][2] = {};

    for (int k0 = 0; k0 < 128; k0 += 32) {
        for (int gi = tid; gi < 1024; gi += 256) {
            int m = gi >> 3, k4 = gi & 7;
            int row = m0 + m;
            float4 v = make_float4(0.f, 0.f, 0.f, 0.f);
            if (row < M) v = *(const float4*)&X[(size_t)row * 128 + k0 + k4 * 4];
            XsT[(k4 * 4 + 0) * 132 + m] = v.x;
            XsT[(k4 * 4 + 1) * 132 + m] = v.y;
            XsT[(k4 * 4 + 2) * 132 + m] = v.z;
            XsT[(k4 * 4 + 3) * 132 + m] = v.w;
        }
        for (int gi = tid; gi < 512; gi += 256) {
            int kk = gi >> 4, n4 = gi & 15;
            float4 v = *(const float4*)&W[(size_t)(k0 + kk) * Ncols + n0 + n4 * 4];
            *(float4*)&Ws[kk * 68 + n4 * 4] = v;
        }
        __syncthreads();
        #pragma unroll 8
        for (int kk = 0; kk < 32; kk++) {
            ulonglong2 w2 = *(const ulonglong2*)&Ws[kk * 68 + tx * 4];
            float4 a03 = *(const float4*)&XsT[kk * 132 + ty * 8];
            float4 a47 = *(const float4*)&XsT[kk * 132 + ty * 8 + 4];
            float av[8] = {a03.x, a03.y, a03.z, a03.w, a47.x, a47.y, a47.z, a47.w};
            #pragma unroll
            for (int i = 0; i < 8; i++) {
                u64 a2 = pack2s(av[i]);
                acc[i][0] = ffma2(a2, w2.x, acc[i][0]);
                acc[i][1] = ffma2(a2, w2.y, acc[i][1]);
            }
        }
        __syncthreads();
    }

    float4 bv = *(const float4*)&bias[n0 + tx * 4];
    #pragma unroll
    for (int i = 0; i < 8; i++) {
        int row = m0 + ty * 8 + i;
        if (row < M) {
            float2 p0 = unpk(acc[i][0]), p1 = unpk(acc[i][1]);
            float4 o = make_float4(p0.x + bv.x, p0.y + bv.y, p1.x + bv.z, p1.y + bv.w);
            *(float4*)&Y[(size_t)row * Ncols + n0 + tx * 4] = o;
        }
    }
}

// ---------------- Phase A: edge-parallel alpha via tiled GEMM ----------------
// 128-edge tile per block; thread tile = 8 edges x 8 channels; no shuffles.
template <int HC>
__global__ __launch_bounds__(2 * HC) void phaseA_kernel(
    const int* __restrict__ ei, const float* __restrict__ ea,
    const float* __restrict__ We, const float* __restrict__ att)
{
    constexpr int H = HC / 64, CCG = HC / 8, NT = 2 * HC;
    constexpr int STR = CCG + 1;

    __shared__ float sWe[32 * HC];
    __shared__ float sEAT[32 * 132];   // [k][edge], reused as sPart after GEMM
    __shared__ int sS[128], sD[128];

    int tid = threadIdx.x;
    int e0 = blockIdx.x * 128;
    const int* src = ei;
    const int* dst = ei + N_EDGES;

    for (int i = tid; i < 128; i += NT) {
        int eid = e0 + i;
        int s = 0, d = 0;
        if (eid < N_EDGES)      { s = src[eid]; d = dst[eid]; }
        else if (eid < ETOT)    { s = d = eid - N_EDGES; }
        sS[i] = s; sD[i] = d;
    }
    for (int i = tid; i < 32 * HC; i += NT) sWe[i] = We[i];
    for (int gi = tid; gi < 1024; gi += NT) {
        int e = gi >> 3, k4 = gi & 7;
        int eid = e0 + e;
        float4 v = make_float4(0.f, 0.f, 0.f, 0.f);
        if (eid < N_EDGES)   v = *(const float4*)&ea[(size_t)eid * 32 + k4 * 4];
        else if (eid < ETOT) v = *(const float4*)&d_ealoop[(size_t)(eid - N_EDGES) * 32 + k4 * 4];
        sEAT[(k4 * 4 + 0) * 132 + e] = v.x;
        sEAT[(k4 * 4 + 1) * 132 + e] = v.y;
        sEAT[(k4 * 4 + 2) * 132 + e] = v.z;
        sEAT[(k4 * 4 + 3) * 132 + e] = v.w;
    }
    __syncthreads();

    int cc = tid % CCG, eg = tid / CCG;

    u64 acc[8][4] = {};
    #pragma unroll 4
    for (int k = 0; k < 32; k++) {
        ulonglong2 w01 = *(const ulonglong2*)&sWe[k * HC + cc * 8];
        ulonglong2 w23 = *(const ulonglong2*)&sWe[k * HC + cc * 8 + 4];
        float4 a03 = *(const float4*)&sEAT[k * 132 + eg * 8];
        float4 a47 = *(const float4*)&sEAT[k * 132 + eg * 8 + 4];
        float av[8] = {a03.x, a03.y, a03.z, a03.w, a47.x, a47.y, a47.z, a47.w};
        #pragma unroll
        for (int e2 = 0; e2 < 8; e2++) {
            u64 a2 = pack2s(av[e2]);
            acc[e2][0] = ffma2(a2, w01.x, acc[e2][0]);
            acc[e2][1] = ffma2(a2, w01.y, acc[e2][1]);
            acc[e2][2] = ffma2(a2, w23.x, acc[e2][2]);
            acc[e2][3] = ffma2(a2, w23.y, acc[e2][3]);
        }
    }

    const float* xl = (HC == 128) ? d_xl1 : d_xl2;
    const float* xr = (HC == 128) ? d_xr1 : d_xr2;
    float att8[8];
    #pragma unroll
    for (int j = 0; j < 8; j++) att8[j] = att[cc * 8 + j];

    float part[8];
    #pragma unroll
    for (int e2 = 0; e2 < 8; e2++) {
        int el = eg * 8 + e2;
        int s = sS[el], d = sD[el];
        float4 l0 = *(const float4*)&xl[(size_t)s * HC + cc * 8];
        float4 l1 = *(const float4*)&xl[(size_t)s * HC + cc * 8 + 4];
        float4 r0 = *(const float4*)&xr[(size_t)d * HC + cc * 8];
        float4 r1 = *(const float4*)&xr[(size_t)d * HC + cc * 8 + 4];
        float2 p0 = unpk(acc[e2][0]), p1 = unpk(acc[e2][1]);
        float2 p2 = unpk(acc[e2][2]), p3 = unpk(acc[e2][3]);
        float u[8] = { p0.x + l0.x + r0.x, p0.y + l0.y + r0.y,
                       p1.x + l0.z + r0.z, p1.y + l0.w + r0.w,
                       p2.x + l1.x + r1.x, p2.y + l1.y + r1.y,
                       p3.x + l1.z + r1.z, p3.y + l1.w + r1.w };
        float pp = 0.f;
        #pragma unroll
        for (int j = 0; j < 8; j++) {
            float lr = fmaxf(u[j], 0.f) + 0.2f * fminf(u[j], 0.f);
            pp = fmaf(att8[j], lr, pp);
        }
        part[e2] = pp;
    }
    __syncthreads();   // done with sEAT as A-tile; reuse as partial buffer

    float* sPart = sEAT;
    #pragma unroll
    for (int e2 = 0; e2 < 8; e2++) sPart[(eg * 8 + e2) * STR + cc] = part[e2];
    __syncthreads();

    for (int i = tid; i < 128 * H; i += NT) {
        int e = i & 127, hh = i >> 7;
        float ssum = 0.f;
        #pragma unroll
        for (int g = 0; g < 8; g++) ssum += sPart[e * STR + hh * 8 + g];
        int eid = e0 + e;
        if (eid < ETOT) d_alpha[(size_t)eid * H + hh] = ssum;
    }
}

// ---------------- Phase B: warp-per-node softmax aggregate (no shuffles) ----------
template <int HC>
__global__ __launch_bounds__(256) void phaseB_kernel(const float* __restrict__ bias)
{
    constexpr int H = HC / 64;
    constexpr bool HB = (HC == 192);
    const float* xl = (HC == 128) ? d_xl1 : d_xl2;
    float*       h  = (HC == 128) ? d_h1  : d_h2;

    int warp = threadIdx.x >> 5, lane = threadIdx.x & 31;
    int node = blockIdx.x * 8 + warp;
    if (node >= N_NODES) return;

    int cA = 4 * lane;
    int hA = lane >> 4;
    int r0 = d_rowptr[node], deg = d_rowptr[node + 1] - r0;
    int selfEid = N_EDGES + node;

    // pass 1: per-head max (2 independent chains)
    float m0 = d_alpha[(size_t)selfEid * H + hA], m1 = -1e30f;
    float mB0 = HB ? d_alpha[(size_t)selfEid * H + 2] : 0.f, mB1 = -1e30f;
    int j = 0;
    for (; j + 1 < deg; j += 2) {
        int ea0 = d_csr[r0 + j].y, ea1 = d_csr[r0 + j + 1].y;
        m0 = fmaxf(m0, d_alpha[(size_t)ea0 * H + hA]);
        m1 = fmaxf(m1, d_alpha[(size_t)ea1 * H + hA]);
        if (HB) {
            mB0 = fmaxf(mB0, d_alpha[(size_t)ea0 * H + 2]);
            mB1 = fmaxf(mB1, d_alpha[(size_t)ea1 * H + 2]);
        }
    }
    if (j < deg) {
        int ea0 = d_csr[r0 + j].y;
        m0 = fmaxf(m0, d_alpha[(size_t)ea0 * H + hA]);
        if (HB) mB0 = fmaxf(mB0, d_alpha[(size_t)ea0 * H + 2]);
    }
    float mA = fmaxf(m0, m1);
    float mB = HB ? fmaxf(mB0, mB1) : 0.f;

    // pass 2: denom + weighted accumulate in one sweep
    float sA = 0.f, sB = 0.f;
    u64 acc0 = 0, acc1 = 0, accB = 0;
    for (j = 0; j < deg; j++) {
        int2 sr = d_csr[r0 + j];
        float aA = d_alpha[(size_t)sr.y * H + hA];
        float pA = __expf(aA - mA);
        ulonglong2 xA = *(const ulonglong2*)&xl[(size_t)sr.x * HC + cA];
        u64 p2 = pack2s(pA);
        acc0 = ffma2(p2, xA.x, acc0);
        acc1 = ffma2(p2, xA.y, acc1);
        sA += pA;
        if (HB) {
            float aB = d_alpha[(size_t)sr.y * H + 2];
            float pB = __expf(aB - mB);
            u64 xB = *(const u64*)&xl[(size_t)sr.x * HC + 128 + 2 * lane];
            accB = ffma2(pack2s(pB), xB, accB);
            sB += pB;
        }
    }
    {   // self loop
        float aA = d_alpha[(size_t)selfEid * H + hA];
        float pA = __expf(aA - mA);
        ulonglong2 xA = *(const ulonglong2*)&xl[(size_t)node * HC + cA];
        u64 p2 = pack2s(pA);
        acc0 = ffma2(p2, xA.x, acc0);
        acc1 = ffma2(p2, xA.y, acc1);
        sA += pA;
        if (HB) {
            float aB = d_alpha[(size_t)selfEid * H + 2];
            float pB = __expf(aB - mB);
            u64 xB = *(const u64*)&xl[(size_t)node * HC + 128 + 2 * lane];
            accB = ffma2(pack2s(pB), xB, accB);
            sB += pB;
        }
    }

    float invA = 1.f / sA;
    float2 a0 = unpk(acc0), a1 = unpk(acc1);
    float4 o;
    o.x = lr01(a0.x * invA + bias[cA + 0]);
    o.y = lr01(a0.y * invA + bias[cA + 1]);
    o.z = lr01(a1.x * invA + bias[cA + 2]);
    o.w = lr01(a1.y * invA + bias[cA + 3]);
    *(float4*)&h[(size_t)node * HC + cA] = o;
    if (HB) {
        float invB = 1.f / sB;
        float2 ab = unpk(accB);
        float2 ob;
        ob.x = lr01(ab.x * invB + bias[128 + 2 * lane + 0]);
        ob.y = lr01(ab.y * invB + bias[128 + 2 * lane + 1]);
        *(float2*)&h[(size_t)node * HC + 128 + 2 * lane] = ob;
    }
}

// ---------------- global_add_pool ----------------
__global__ void pool_kernel(const int* __restrict__ batch) {
    __shared__ float acc[G_GRAPHS * 192];
    int c = threadIdx.x;  // 0..191
    for (int i = c; i < G_GRAPHS * 192; i += 192) acc[i] = 0.f;
    __syncthreads();
    int per = (N_NODES + gridDim.x - 1) / gridDim.x;
    int lo = blockIdx.x * per;
    int hi = min(lo + per, N_NODES);
    for (int n = lo; n < hi; n++) {
        int b = batch[n];
        acc[b * 192 + c] += d_h2[(size_t)n * 192 + c];
    }
    __syncthreads();
    for (int i = c; i < G_GRAPHS * 192; i += 192) atomicAdd(&d_pool[i], acc[i]);
}

// ---------------- MLP head ----------------
__global__ void mlp_kernel(
    const float* __restrict__ W1, const float* __restrict__ c1,
    const float* __restrict__ W2, const float* __restrict__ c2,
    const float* __restrict__ W3, const float* __restrict__ c3,
    const float* __restrict__ W4, const float* __restrict__ c4,
    const float* __restrict__ W5, const float* __restrict__ c5,
    const float* __restrict__ W6, const float* __restrict__ c6,
    float* __restrict__ out)
{
    __shared__ float sa[G_GRAPHS * 192];
    __shared__ float sb[G_GRAPHS * 64];
    int t = threadIdx.x;
    for (int i = t; i < G_GRAPHS * 192; i += 512) sa[i] = d_pool[i];
    __syncthreads();
    if (t < 512) {
        int i = t >> 6, j = t & 63;
        float v = c1[j];
        for (int k = 0; k < 192; k++) v += sa[i * 192 + k] * W1[k * 64 + j];
        sb[t] = lr01(v);
    }
    __syncthreads();
    if (t < 256) {
        int i = t >> 5, j = t & 31;
        float v = c2[j];
        for (int k = 0; k < 64; k++) v += sb[i * 64 + k] * W2[k * 32 + j];
        sa[t] = lr01(v);
    }
    __syncthreads();
    if (t < 128) {
        int i = t >> 4, j = t & 15;
        float v = c3[j];
        for (int k = 0; k < 32; k++) v += sa[i * 32 + k] * W3[k * 16 + j];
        sb[t] = lr01(v);
    }
    __syncthreads();
    if (t < 64) {
        int i = t >> 3, j = t & 7;
        float v = c4[j];
        for (int k = 0; k < 16; k++) v += sb[i * 16 + k] * W4[k * 8 + j];
        sa[t] = lr01(v);
    }
    __syncthreads();
    if (t < G_GRAPHS) {
        float v = c5[0];
        for (int k = 0; k < 8; k++) v += sa[t * 8 + k] * W5[k];
        out[t] = v * W6[0] + c6[0];
    }
}

// ---------------- launcher ----------------
extern "C" void kernel_launch(void* const* d_in, const int* in_sizes, int n_in,
                              void* d_out, int out_size)
{
    const float* x     = (const float*)d_in[0];
    const int*   ei    = (const int*)  d_in[1];
    const float* ea    = (const float*)d_in[2];
    const int*   batch = (const int*)  d_in[3];
    const float* Wl1 = (const float*)d_in[4];  const float* bl1 = (const float*)d_in[5];
    const float* Wr1 = (const float*)d_in[6];  const float* br1 = (const float*)d_in[7];
    const float* We1 = (const float*)d_in[8];  const float* att1 = (const float*)d_in[9];
    const float* bias1 = (const float*)d_in[10];
    const float* Wl2 = (const float*)d_in[11]; const float* bl2 = (const float*)d_in[12];
    const float* Wr2 = (const float*)d_in[13]; const float* br2 = (const float*)d_in[14];
    const float* We2 = (const float*)d_in[15]; const float* att2 = (const float*)d_in[16];
    const float* bias2 = (const float*)d_in[17];
    const float* W1 = (const float*)d_in[18]; const float* c1 = (const float*)d_in[19];
    const float* W2 = (const float*)d_in[20]; const float* c2 = (const float*)d_in[21];
    const float* W3 = (const float*)d_in[22]; const float* c3 = (const float*)d_in[23];
    const float* W4 = (const float*)d_in[24]; const float* c4 = (const float*)d_in[25];
    const float* W5 = (const float*)d_in[26]; const float* c5 = (const float*)d_in[27];
    const float* W6 = (const float*)d_in[28]; const float* c6 = (const float*)d_in[29];
    float* out = (float*)d_out;

    const int* src = ei;
    const int* dst = ei + N_EDGES;

    const int ATILES = (ETOT + 127) / 128;     // 6641
    const int GX = (N_NODES + 127) / 128;      // 391
    const int NB = (N_NODES + 7) / 8;          // 6250

    // CSR build + self-loop edge attrs
    zero_kernel<<<(N_NODES + 255) / 256, 256>>>();
    hist_kernel<<<(N_EDGES + 255) / 256, 256>>>(dst);
    scan_kernel<<<1, 1024>>>();
    scatter_kernel<<<(N_EDGES + 255) / 256, 256>>>(src, dst);
    ealoop_kernel<<<NB, 256>>>(ea);

    // Layer 1
    gemm_k128<<<dim3(GX, 2), 256>>>(x, 0, Wl1, bl1, 0, N_NODES, 128);
    gemm_k128<<<dim3(GX, 2), 256>>>(x, 0, Wr1, br1, 1, N_NODES, 128);
    phaseA_kernel<128><<<ATILES, 256>>>(ei, ea, We1, att1);
    phaseB_kernel<128><<<NB, 256>>>(bias1);

    // Layer 2
    gemm_k128<<<dim3(GX, 3), 256>>>(nullptr, 1, Wl2, bl2, 2, N_NODES, 192);
    gemm_k128<<<dim3(GX, 3), 256>>>(nullptr, 1, Wr2, br2, 3, N_NODES, 192);
    phaseA_kernel<192><<<ATILES, 384>>>(ei, ea, We2, att2);
    phaseB_kernel<192><<<NB, 256>>>(bias2);

    // Pool + MLP
    pool_kernel<<<128, 192>>>(batch);
    mlp_kernel<<<1, 512>>>(W1, c1, W2, c2, W3, c3, W4, c4, W5, c5, W6, c6, out);
}

// round 4
// speedup vs baseline: 1.0323x; 1.0323x over previous
#include <cuda_runtime.h>
#include <math.h>

#define N_NODES 50000
#define N_EDGES 800000
#define ETOT    (N_EDGES + N_NODES)
#define G_GRAPHS 8

typedef unsigned long long u64;

__device__ __forceinline__ u64 pack2s(float a) {
    u64 r; asm("mov.b64 %0,{%1,%1};" : "=l"(r) : "f"(a)); return r;
}
__device__ __forceinline__ float2 unpk(u64 v) {
    float2 f; asm("mov.b64 {%0,%1},%2;" : "=f"(f.x), "=f"(f.y) : "l"(v)); return f;
}
__device__ __forceinline__ u64 ffma2(u64 a, u64 b, u64 c) {
    u64 d; asm("fma.rn.f32x2 %0,%1,%2,%3;" : "=l"(d) : "l"(a), "l"(b), "l"(c)); return d;
}

// ---------------- scratch ----------------
__device__ float d_xl1[N_NODES * 128];
__device__ float d_xr1[N_NODES * 128];
__device__ float d_h1 [N_NODES * 128];
__device__ float d_xl2[N_NODES * 192];
__device__ float d_xr2[N_NODES * 192];
__device__ float d_h2 [N_NODES * 192];
__device__ int   d_rowptr[N_NODES + 1];
__device__ int   d_counts[N_NODES];
__device__ int   d_cursor[N_NODES];
__device__ int2  d_csr[N_EDGES];                 // (src, eid) grouped by dst
__device__ float d_ealoop[N_NODES * 32];         // mean incoming edge attr
__device__ int2  d_slots[ETOT];                  // (src, eaIdx) dst-grouped, self-loops inline
__device__ int   d_sdst[ETOT];                   // dst node of each slot
__device__ float d_alpha[(size_t)ETOT * 3];      // per-slot attention logits
__device__ float d_pool[G_GRAPHS * 192];

__device__ __forceinline__ float lr01(float x) { return x > 0.f ? x : 0.01f * x; }

// ---------------- CSR build ----------------
__global__ void zero_kernel() {
    int i = blockIdx.x * blockDim.x + threadIdx.x;
    if (i < N_NODES) { d_counts[i] = 0; d_cursor[i] = 0; }
    if (i < G_GRAPHS * 192) d_pool[i] = 0.f;
}

__global__ void hist_kernel(const int* __restrict__ dst) {
    int e = blockIdx.x * blockDim.x + threadIdx.x;
    if (e < N_EDGES) atomicAdd(&d_counts[dst[e]], 1);
}

__global__ void scan_kernel() {
    __shared__ int sh[1024];
    int t = threadIdx.x;
    const int CH = (N_NODES + 1023) / 1024;
    int lo = t * CH;
    int hi = min(lo + CH, N_NODES);
    int s = 0;
    for (int i = lo; i < hi; i++) s += d_counts[i];
    sh[t] = s;
    __syncthreads();
    for (int off = 1; off < 1024; off <<= 1) {
        int v = (t >= off) ? sh[t - off] : 0;
        __syncthreads();
        sh[t] += v;
        __syncthreads();
    }
    int run = (t > 0) ? sh[t - 1] : 0;
    for (int i = lo; i < hi; i++) { d_rowptr[i] = run; run += d_counts[i]; }
    if (t == 0) d_rowptr[N_NODES] = N_EDGES;
}

__global__ void scatter_kernel(const int* __restrict__ src, const int* __restrict__ dst) {
    int e = blockIdx.x * blockDim.x + threadIdx.x;
    if (e < N_EDGES) {
        int d = dst[e];
        int p = atomicAdd(&d_cursor[d], 1);
        d_csr[d_rowptr[d] + p] = make_int2(src[e], e);
    }
}

// ---------------- ea_loop = mean of incoming edge attrs per node ----------------
__global__ void ealoop_kernel(const float* __restrict__ ea) {
    int warp = threadIdx.x >> 5, lane = threadIdx.x & 31;
    int node = blockIdx.x * 8 + warp;
    if (node >= N_NODES) return;
    int r0 = d_rowptr[node], deg = d_rowptr[node + 1] - r0;
    float s = 0.f;
    for (int j = 0; j < deg; j++) {
        int eid = d_csr[r0 + j].y;
        s += ea[(size_t)eid * 32 + lane];
    }
    d_ealoop[(size_t)node * 32 + lane] = s * (1.f / (float)max(deg, 1));
}

// ---------------- slot array: dst-grouped edges with inline self-loops ----------
// node n's slots = [rowptr[n]+n, rowptr[n+1]+n+1); last slot is the self-loop.
__global__ void build_slots_kernel() {
    int warp = threadIdx.x >> 5, lane = threadIdx.x & 31;
    int node = blockIdx.x * 8 + warp;
    if (node >= N_NODES) return;
    int r0 = d_rowptr[node], deg = d_rowptr[node + 1] - r0;
    int base = r0 + node;
    for (int j = lane; j < deg; j += 32) {
        d_slots[base + j] = d_csr[r0 + j];       // (src, eid)
        d_sdst[base + j] = node;
    }
    if (lane == 0) {
        d_slots[base + deg] = make_int2(node, N_EDGES + node);  // self loop
        d_sdst[base + deg] = node;
    }
}

// ---------------- GEMM: Y[M,Ncols] = X[M,128] @ W[128,Ncols] + bias ----------------
__global__ __launch_bounds__(256) void gemm_k128(
    const float* __restrict__ Xin, int useH1,
    const float* __restrict__ W, const float* __restrict__ bias,
    int outSel, int M, int Ncols)
{
    const float* X = useH1 ? d_h1 : Xin;
    float* Y = (outSel == 0) ? d_xl1 : (outSel == 1) ? d_xr1 : (outSel == 2) ? d_xl2 : d_xr2;

    __shared__ float XsT[32 * 132];  // [k][m]
    __shared__ float Ws [32 * 68];   // [k][n]

    int tid = threadIdx.x;
    int tx = tid & 15, ty = tid >> 4;
    int m0 = blockIdx.x * 128, n0 = blockIdx.y * 64;

    u64 acc[8][2] = {};

    for (int k0 = 0; k0 < 128; k0 += 32) {
        for (int gi = tid; gi < 1024; gi += 256) {
            int m = gi >> 3, k4 = gi & 7;
            int row = m0 + m;
            float4 v = make_float4(0.f, 0.f, 0.f, 0.f);
            if (row < M) v = *(const float4*)&X[(size_t)row * 128 + k0 + k4 * 4];
            XsT[(k4 * 4 + 0) * 132 + m] = v.x;
            XsT[(k4 * 4 + 1) * 132 + m] = v.y;
            XsT[(k4 * 4 + 2) * 132 + m] = v.z;
            XsT[(k4 * 4 + 3) * 132 + m] = v.w;
        }
        for (int gi = tid; gi < 512; gi += 256) {
            int kk = gi >> 4, n4 = gi & 15;
            float4 v = *(const float4*)&W[(size_t)(k0 + kk) * Ncols + n0 + n4 * 4];
            *(float4*)&Ws[kk * 68 + n4 * 4] = v;
        }
        __syncthreads();
        #pragma unroll 8
        for (int kk = 0; kk < 32; kk++) {
            ulonglong2 w2 = *(const ulonglong2*)&Ws[kk * 68 + tx * 4];
            float4 a03 = *(const float4*)&XsT[kk * 132 + ty * 8];
            float4 a47 = *(const float4*)&XsT[kk * 132 + ty * 8 + 4];
            float av[8] = {a03.x, a03.y, a03.z, a03.w, a47.x, a47.y, a47.z, a47.w};
            #pragma unroll
            for (int i = 0; i < 8; i++) {
                u64 a2 = pack2s(av[i]);
                acc[i][0] = ffma2(a2, w2.x, acc[i][0]);
                acc[i][1] = ffma2(a2, w2.y, acc[i][1]);
            }
        }
        __syncthreads();
    }

    float4 bv = *(const float4*)&bias[n0 + tx * 4];
    #pragma unroll
    for (int i = 0; i < 8; i++) {
        int row = m0 + ty * 8 + i;
        if (row < M) {
            float2 p0 = unpk(acc[i][0]), p1 = unpk(acc[i][1]);
            float4 o = make_float4(p0.x + bv.x, p0.y + bv.y, p1.x + bv.z, p1.y + bv.w);
            *(float4*)&Y[(size_t)row * Ncols + n0 + tx * 4] = o;
        }
    }
}

// ---------------- Phase A: slot-parallel alpha via tiled GEMM ----------------
// 128 dst-grouped slots per block (xr[d] gets L1 reuse); 8 slots x 8 ch per thread.
template <int HC>
__global__ __launch_bounds__(2 * HC) void phaseA_kernel(
    const float* __restrict__ ea,
    const float* __restrict__ We, const float* __restrict__ att)
{
    constexpr int H = HC / 64, CCG = HC / 8, NT = 2 * HC;
    constexpr int STR = CCG + 1;

    __shared__ float sWe[32 * HC];
    __shared__ float sEAT[32 * 132];   // [k][slot], reused as sPart after GEMM
    __shared__ int sS[128], sD[128], sE[128];

    int tid = threadIdx.x;
    int e0 = blockIdx.x * 128;

    for (int i = tid; i < 128; i += NT) {
        int gs = e0 + i;
        int s = 0, d = 0, eidx = N_EDGES;   // dummy slot -> node 0 / ealoop[0]
        if (gs < ETOT) {
            int2 sl = d_slots[gs];
            s = sl.x; eidx = sl.y; d = d_sdst[gs];
        }
        sS[i] = s; sD[i] = d; sE[i] = eidx;
    }
    __syncthreads();

    for (int i = tid; i < 32 * HC; i += NT) sWe[i] = We[i];
    for (int gi = tid; gi < 1024; gi += NT) {
        int e = gi >> 3, k4 = gi & 7;
        int eidx = sE[e];
        const float* row = (eidx < N_EDGES) ? (ea + (size_t)eidx * 32)
                                            : (d_ealoop + (size_t)(eidx - N_EDGES) * 32);
        float4 v = *(const float4*)(row + k4 * 4);
        sEAT[(k4 * 4 + 0) * 132 + e] = v.x;
        sEAT[(k4 * 4 + 1) * 132 + e] = v.y;
        sEAT[(k4 * 4 + 2) * 132 + e] = v.z;
        sEAT[(k4 * 4 + 3) * 132 + e] = v.w;
    }
    __syncthreads();

    int cc = tid % CCG, eg = tid / CCG;

    u64 acc[8][4] = {};
    #pragma unroll 4
    for (int k = 0; k < 32; k++) {
        ulonglong2 w01 = *(const ulonglong2*)&sWe[k * HC + cc * 8];
        ulonglong2 w23 = *(const ulonglong2*)&sWe[k * HC + cc * 8 + 4];
        float4 a03 = *(const float4*)&sEAT[k * 132 + eg * 8];
        float4 a47 = *(const float4*)&sEAT[k * 132 + eg * 8 + 4];
        float av[8] = {a03.x, a03.y, a03.z, a03.w, a47.x, a47.y, a47.z, a47.w};
        #pragma unroll
        for (int e2 = 0; e2 < 8; e2++) {
            u64 a2 = pack2s(av[e2]);
            acc[e2][0] = ffma2(a2, w01.x, acc[e2][0]);
            acc[e2][1] = ffma2(a2, w01.y, acc[e2][1]);
            acc[e2][2] = ffma2(a2, w23.x, acc[e2][2]);
            acc[e2][3] = ffma2(a2, w23.y, acc[e2][3]);
        }
    }

    const float* xl = (HC == 128) ? d_xl1 : d_xl2;
    const float* xr = (HC == 128) ? d_xr1 : d_xr2;
    float att8[8];
    #pragma unroll
    for (int j = 0; j < 8; j++) att8[j] = att[cc * 8 + j];

    float part[8];
    #pragma unroll
    for (int e2 = 0; e2 < 8; e2++) {
        int el = eg * 8 + e2;
        int s = sS[el], d = sD[el];
        float4 l0 = *(const float4*)&xl[(size_t)s * HC + cc * 8];
        float4 l1 = *(const float4*)&xl[(size_t)s * HC + cc * 8 + 4];
        float4 r0 = *(const float4*)&xr[(size_t)d * HC + cc * 8];   // L1: d repeats
        float4 r1 = *(const float4*)&xr[(size_t)d * HC + cc * 8 + 4];
        float2 p0 = unpk(acc[e2][0]), p1 = unpk(acc[e2][1]);
        float2 p2 = unpk(acc[e2][2]), p3 = unpk(acc[e2][3]);
        float u[8] = { p0.x + l0.x + r0.x, p0.y + l0.y + r0.y,
                       p1.x + l0.z + r0.z, p1.y + l0.w + r0.w,
                       p2.x + l1.x + r1.x, p2.y + l1.y + r1.y,
                       p3.x + l1.z + r1.z, p3.y + l1.w + r1.w };
        float pp = 0.f;
        #pragma unroll
        for (int j = 0; j < 8; j++) {
            float lr = fmaxf(u[j], 0.f) + 0.2f * fminf(u[j], 0.f);
            pp = fmaf(att8[j], lr, pp);
        }
        part[e2] = pp;
    }
    __syncthreads();   // done with sEAT; reuse as partial buffer

    float* sPart = sEAT;
    #pragma unroll
    for (int e2 = 0; e2 < 8; e2++) sPart[(eg * 8 + e2) * STR + cc] = part[e2];
    __syncthreads();

    for (int i = tid; i < 128 * H; i += NT) {
        int e = i & 127, hh = i >> 7;
        float ssum = 0.f;
        #pragma unroll
        for (int g = 0; g < 8; g++) ssum += sPart[e * STR + hh * 8 + g];
        int gs = e0 + e;
        if (gs < ETOT) d_alpha[(size_t)gs * H + hh] = ssum;
    }
}

// ---------------- Phase B: warp-per-node softmax aggregate, sequential slots ------
template <int HC>
__global__ __launch_bounds__(256) void phaseB_kernel(const float* __restrict__ bias)
{
    constexpr int H = HC / 64;
    constexpr bool HB = (HC == 192);
    const float* xl = (HC == 128) ? d_xl1 : d_xl2;
    float*       h  = (HC == 128) ? d_h1  : d_h2;

    int warp = threadIdx.x >> 5, lane = threadIdx.x & 31;
    int node = blockIdx.x * 8 + warp;
    if (node >= N_NODES) return;

    int cA = 4 * lane;
    int hA = lane >> 4;
    int r0 = d_rowptr[node];
    int cnt = d_rowptr[node + 1] - r0 + 1;       // edges + self loop
    int base = r0 + node;                        // slot base

    // pass 1: per-head max over contiguous alpha
    float m0 = -1e30f, m1 = -1e30f, mB0 = -1e30f, mB1 = -1e30f;
    int j = 0;
    for (; j + 1 < cnt; j += 2) {
        m0 = fmaxf(m0, d_alpha[(size_t)(base + j) * H + hA]);
        m1 = fmaxf(m1, d_alpha[(size_t)(base + j + 1) * H + hA]);
        if (HB) {
            mB0 = fmaxf(mB0, d_alpha[(size_t)(base + j) * H + 2]);
            mB1 = fmaxf(mB1, d_alpha[(size_t)(base + j + 1) * H + 2]);
        }
    }
    if (j < cnt) {
        m0 = fmaxf(m0, d_alpha[(size_t)(base + j) * H + hA]);
        if (HB) mB0 = fmaxf(mB0, d_alpha[(size_t)(base + j) * H + 2]);
    }
    float mA = fmaxf(m0, m1);
    float mB = HB ? fmaxf(mB0, mB1) : 0.f;

    // pass 2: denom + weighted accumulate
    float sA = 0.f, sB = 0.f;
    u64 acc0 = 0, acc1 = 0, accB = 0;
    for (j = 0; j < cnt; j++) {
        int srcn = d_slots[base + j].x;
        float aA = d_alpha[(size_t)(base + j) * H + hA];
        float pA = __expf(aA - mA);
        ulonglong2 xA = *(const ulonglong2*)&xl[(size_t)srcn * HC + cA];
        u64 p2 = pack2s(pA);
        acc0 = ffma2(p2, xA.x, acc0);
        acc1 = ffma2(p2, xA.y, acc1);
        sA += pA;
        if (HB) {
            float aB = d_alpha[(size_t)(base + j) * H + 2];
            float pB = __expf(aB - mB);
            u64 xB = *(const u64*)&xl[(size_t)srcn * HC + 128 + 2 * lane];
            accB = ffma2(pack2s(pB), xB, accB);
            sB += pB;
        }
    }

    float invA = 1.f / sA;
    float2 a0 = unpk(acc0), a1 = unpk(acc1);
    float4 o;
    o.x = lr01(a0.x * invA + bias[cA + 0]);
    o.y = lr01(a0.y * invA + bias[cA + 1]);
    o.z = lr01(a1.x * invA + bias[cA + 2]);
    o.w = lr01(a1.y * invA + bias[cA + 3]);
    *(float4*)&h[(size_t)node * HC + cA] = o;
    if (HB) {
        float invB = 1.f / sB;
        float2 ab = unpk(accB);
        float2 ob;
        ob.x = lr01(ab.x * invB + bias[128 + 2 * lane + 0]);
        ob.y = lr01(ab.y * invB + bias[128 + 2 * lane + 1]);
        *(float2*)&h[(size_t)node * HC + 128 + 2 * lane] = ob;
    }
}

// ---------------- global_add_pool ----------------
__global__ void pool_kernel(const int* __restrict__ batch) {
    __shared__ float acc[G_GRAPHS * 192];
    int c = threadIdx.x;  // 0..191
    for (int i = c; i < G_GRAPHS * 192; i += 192) acc[i] = 0.f;
    __syncthreads();
    int per = (N_NODES + gridDim.x - 1) / gridDim.x;
    int lo = blockIdx.x * per;
    int hi = min(lo + per, N_NODES);
    for (int n = lo; n < hi; n++) {
        int b = batch[n];
        acc[b * 192 + c] += d_h2[(size_t)n * 192 + c];
    }
    __syncthreads();
    for (int i = c; i < G_GRAPHS * 192; i += 192) atomicAdd(&d_pool[i], acc[i]);
}

// ---------------- MLP head ----------------
__global__ void mlp_kernel(
    const float* __restrict__ W1, const float* __restrict__ c1,
    const float* __restrict__ W2, const float* __restrict__ c2,
    const float* __restrict__ W3, const float* __restrict__ c3,
    const float* __restrict__ W4, const float* __restrict__ c4,
    const float* __restrict__ W5, const float* __restrict__ c5,
    const float* __restrict__ W6, const float* __restrict__ c6,
    float* __restrict__ out)
{
    __shared__ float sa[G_GRAPHS * 192];
    __shared__ float sb[G_GRAPHS * 64];
    int t = threadIdx.x;
    for (int i = t; i < G_GRAPHS * 192; i += 512) sa[i] = d_pool[i];
    __syncthreads();
    if (t < 512) {
        int i = t >> 6, j = t & 63;
        float v = c1[j];
        for (int k = 0; k < 192; k++) v += sa[i * 192 + k] * W1[k * 64 + j];
        sb[t] = lr01(v);
    }
    __syncthreads();
    if (t < 256) {
        int i = t >> 5, j = t & 31;
        float v = c2[j];
        for (int k = 0; k < 64; k++) v += sb[i * 64 + k] * W2[k * 32 + j];
        sa[t] = lr01(v);
    }
    __syncthreads();
    if (t < 128) {
        int i = t >> 4, j = t & 15;
        float v = c3[j];
        for (int k = 0; k < 32; k++) v += sa[i * 32 + k] * W3[k * 16 + j];
        sb[t] = lr01(v);
    }
    __syncthreads();
    if (t < 64) {
        int i = t >> 3, j = t & 7;
        float v = c4[j];
        for (int k = 0; k < 16; k++) v += sb[i * 16 + k] * W4[k * 8 + j];
        sa[t] = lr01(v);
    }
    __syncthreads();
    if (t < G_GRAPHS) {
        float v = c5[0];
        for (int k = 0; k < 8; k++) v += sa[t * 8 + k] * W5[k];
        out[t] = v * W6[0] + c6[0];
    }
}

// ---------------- launcher ----------------
extern "C" void kernel_launch(void* const* d_in, const int* in_sizes, int n_in,
                              void* d_out, int out_size)
{
    const float* x     = (const float*)d_in[0];
    const int*   ei    = (const int*)  d_in[1];
    const float* ea    = (const float*)d_in[2];
    const int*   batch = (const int*)  d_in[3];
    const float* Wl1 = (const float*)d_in[4];  const float* bl1 = (const float*)d_in[5];
    const float* Wr1 = (const float*)d_in[6];  const float* br1 = (const float*)d_in[7];
    const float* We1 = (const float*)d_in[8];  const float* att1 = (const float*)d_in[9];
    const float* bias1 = (const float*)d_in[10];
    const float* Wl2 = (const float*)d_in[11]; const float* bl2 = (const float*)d_in[12];
    const float* Wr2 = (const float*)d_in[13]; const float* br2 = (const float*)d_in[14];
    const float* We2 = (const float*)d_in[15]; const float* att2 = (const float*)d_in[16];
    const float* bias2 = (const float*)d_in[17];
    const float* W1 = (const float*)d_in[18]; const float* c1 = (const float*)d_in[19];
    const float* W2 = (const float*)d_in[20]; const float* c2 = (const float*)d_in[21];
    const float* W3 = (const float*)d_in[22]; const float* c3 = (const float*)d_in[23];
    const float* W4 = (const float*)d_in[24]; const float* c4 = (const float*)d_in[25];
    const float* W5 = (const float*)d_in[26]; const float* c5 = (const float*)d_in[27];
    const float* W6 = (const float*)d_in[28]; const float* c6 = (const float*)d_in[29];
    float* out = (float*)d_out;

    const int* src = ei;
    const int* dst = ei + N_EDGES;

    const int ATILES = (ETOT + 127) / 128;     // 6641
    const int GX = (N_NODES + 127) / 128;      // 391
    const int NB = (N_NODES + 7) / 8;          // 6250

    // CSR build + slot array + self-loop edge attrs
    zero_kernel<<<(N_NODES + 255) / 256, 256>>>();
    hist_kernel<<<(N_EDGES + 255) / 256, 256>>>(dst);
    scan_kernel<<<1, 1024>>>();
    scatter_kernel<<<(N_EDGES + 255) / 256, 256>>>(src, dst);
    build_slots_kernel<<<NB, 256>>>();
    ealoop_kernel<<<NB, 256>>>(ea);

    // Layer 1
    gemm_k128<<<dim3(GX, 2), 256>>>(x, 0, Wl1, bl1, 0, N_NODES, 128);
    gemm_k128<<<dim3(GX, 2), 256>>>(x, 0, Wr1, br1, 1, N_NODES, 128);
    phaseA_kernel<128><<<ATILES, 256>>>(ea, We1, att1);
    phaseB_kernel<128><<<NB, 256>>>(bias1);

    // Layer 2
    gemm_k128<<<dim3(GX, 3), 256>>>(nullptr, 1, Wl2, bl2, 2, N_NODES, 192);
    gemm_k128<<<dim3(GX, 3), 256>>>(nullptr, 1, Wr2, br2, 3, N_NODES, 192);
    phaseA_kernel<192><<<ATILES, 384>>>(ea, We2, att2);
    phaseB_kernel<192><<<NB, 256>>>(bias2);

    // Pool + MLP
    pool_kernel<<<128, 192>>>(batch);
    mlp_kernel<<<1, 512>>>(W1, c1, W2, c2, W3, c3, W4, c4, W5, c5, W6, c6, out);
}